// round 9
// baseline (speedup 1.0000x reference)
#include <cuda_runtime.h>
#include <cuda_fp16.h>
#include <stdint.h>

// HybridMixSTEDecoder: 5 disjoint-group GEMMs (27648x512 @ 512xN_i) + bias,
// scattered into out[b, tp*9+p, joint, c]. Groups disjoint -> count/div identity.
//
// Single-pass fp16 mma.sync (A, B RN-rounded fp16, fp32 accum; rel_err ~3e-4).
// A staged RAW f32 in smem via cp.async (deep MLP, zero register cost),
// converted to fp16 at consume; B fp16 staged via cp.async (pre-converted,
// k-permuted in prep_B). Both double-buffered; one commit group per chunk.
// Grid (variant, m-block): CTAs sharing token rows are schedule-adjacent.

// Padded group rows: g0..g4 = 88,88,144,88,88 -> 496 rows of 512 fp16.
static __device__ __align__(16) __half g_Bh[496 * 512];

// ---------------- helpers ----------------
static __device__ __forceinline__ uint32_t s2u(const void* p) {
    uint32_t a;
    asm("{ .reg .u64 t; cvta.to.shared.u64 t, %1; cvt.u32.u64 %0, t; }"
        : "=r"(a) : "l"(p));
    return a;
}
static __device__ __forceinline__ uint32_t f16x2_rn(float lo, float hi) {
    uint32_t r; asm("cvt.rn.f16x2.f32 %0, %1, %2;" : "=r"(r) : "f"(hi), "f"(lo));
    return r;  // low half = lo, high half = hi
}
static __device__ __forceinline__ float4 lds128(uint32_t a) {
    float4 v;
    asm volatile("ld.shared.v4.f32 {%0,%1,%2,%3}, [%4];"
        : "=f"(v.x), "=f"(v.y), "=f"(v.z), "=f"(v.w) : "r"(a));
    return v;
}
static __device__ __forceinline__ void ldsm_x4(uint32_t* r, uint32_t addr) {
    asm volatile("ldmatrix.sync.aligned.m8n8.x4.shared.b16 {%0,%1,%2,%3}, [%4];"
        : "=r"(r[0]), "=r"(r[1]), "=r"(r[2]), "=r"(r[3]) : "r"(addr));
}
static __device__ __forceinline__ void ldsm_x2(uint32_t* r, uint32_t addr) {
    asm volatile("ldmatrix.sync.aligned.m8n8.x2.shared.b16 {%0,%1}, [%2];"
        : "=r"(r[0]), "=r"(r[1]) : "r"(addr));
}
static __device__ __forceinline__ void mma_f16(float* d, const uint32_t* a,
                                               const uint32_t* b) {
    asm volatile(
        "mma.sync.aligned.m16n8k16.row.col.f32.f16.f16.f32 "
        "{%0,%1,%2,%3}, {%4,%5,%6,%7}, {%8,%9}, {%0,%1,%2,%3};"
        : "+f"(d[0]), "+f"(d[1]), "+f"(d[2]), "+f"(d[3])
        : "r"(a[0]), "r"(a[1]), "r"(a[2]), "r"(a[3]), "r"(b[0]), "r"(b[1]));
}
static __device__ __forceinline__ void cp16(uint32_t dst, const void* src, int pred) {
    asm volatile(
        "{\n\t.reg .pred p;\n\tsetp.ne.b32 p, %0, 0;\n\t"
        "@p cp.async.cg.shared.global [%1], [%2], 16;\n\t}"
        :: "r"(pred), "r"(dst), "l"(src));
}

// ---------------- prep: W (f32) -> fp16, [n][512] with per-16k permute ------
// Thread handles 4 consecutive k (o = k&15 in {0,4,8,12}, t = o>>2):
//   halves (k,k+1)   -> eff positions (2t, 2t+1)
//   halves (k+2,k+3) -> eff positions (2t+8, 2t+9)
__global__ void __launch_bounds__(256) prep_B(
    const float* __restrict__ W0, const float* __restrict__ W1,
    const float* __restrict__ W2, const float* __restrict__ W3,
    const float* __restrict__ W4)
{
    int idx = blockIdx.x * 256 + threadIdx.x;   // one thread per (grow, k4)
    if (idx >= 496 * 128) return;
    int grow = idx >> 7;
    int k = (idx & 127) << 2;
    int g, n;
    if      (grow <  88) { g = 0; n = grow;       }
    else if (grow < 176) { g = 1; n = grow -  88; }
    else if (grow < 320) { g = 2; n = grow - 176; }
    else if (grow < 408) { g = 3; n = grow - 320; }
    else                 { g = 4; n = grow - 408; }
    const float* Wg = (g == 0) ? W0 : (g == 1) ? W1 : (g == 2) ? W2
                    : (g == 3) ? W3 : W4;
    int Ng = (g == 2) ? 135 : 81;

    float4 v = make_float4(0.f, 0.f, 0.f, 0.f);
    if (n < Ng) v = *(const float4*)(Wg + n * 512 + k);

    uint32_t h01 = f16x2_rn(v.x, v.y);
    uint32_t h23 = f16x2_rn(v.z, v.w);
    uint32_t* dst = (uint32_t*)g_Bh + grow * 256 + ((k & ~15) >> 1) + ((k >> 2) & 3);
    dst[0] = h01;   // eff (2t, 2t+1)
    dst[4] = h23;   // eff (2t+8, 2t+9)
}

// ---------------- fused core ----------------
// Smem: A stages 0/1 (raw f32, 32KB each, 256B rows, 16B-unit swizzle
// phys = u ^ ((row&3)<<2)), then B stages 0/1 (fp16, 128B rows, XOR swizzle).
template<int NPAD, int GS, int CO>
static __device__ __forceinline__ void decode_core(
    const float* __restrict__ tokens,
    const __half* __restrict__ BhT,
    const float* __restrict__ bias,
    float* __restrict__ out,
    int gidx, int jb3)
{
    constexpr int NT    = NPAD / 8;
    constexpr int PAIRS = NT / 2;
    constexpr int ODD   = NT & 1;
    constexpr int NREAL = (GS == 5) ? 135 : 81;
    constexpr int AB    = 32768;               // A stage bytes
    constexpr int BB    = NPAD * 128;          // B stage bytes
    constexpr int BOFF  = 2 * AB;              // B region base
    constexpr int NB8   = NPAD * 8;            // B cp.async 16B ops
    constexpr int CPIT  = (NB8 + 255) / 256;

    extern __shared__ char smem[];
    const uint32_t su = s2u(smem);

    const int tid  = threadIdx.x;
    const int wid  = tid >> 5;
    const int lane = tid & 31;

    const int m0 = blockIdx.y * 128;
    const float* Abase = tokens + (size_t)m0 * 2560 + gidx * 512;

    // ---- A producer geometry (cp.async f32): piece e = tid + 256*i ----
    //   row = e>>4 (advances 16 per i), fc = e&15 (16B unit within 64-f row)
    const int prow = tid >> 4;
    const int pfc  = tid & 15;
    const float* asrc = Abase + (size_t)prow * 2560 + pfc * 4;
    const uint32_t adst = su + (uint32_t)(prow * 256
                        + ((pfc ^ ((prow & 3) << 2)) << 4));

    // ---- A consumer geometry (LDS.128): rows r1, r1+8; unit (4j+tig)^xr ----
    const int r1  = 16 * wid + (lane >> 2);
    const int tig = lane & 3;
    const int xr  = (r1 & 3) << 2;
    const uint32_t ac1 = su + (uint32_t)(r1 * 256);

    // ---- B ldmatrix geometry ----
    const int rBo = (lane & 7) + ((lane & 16) ? 8 : 0);
    const int kuB = (lane >> 3) & 1;
    const int sw  = lane & 7;

    float acc[NT][4];
    #pragma unroll
    for (int t = 0; t < NT; t++)
        #pragma unroll
        for (int q = 0; q < 4; q++) acc[t][q] = 0.f;

    // ---- prologue: A(0) + B(0) cp.async, one commit group ----
    #pragma unroll
    for (int i = 0; i < 8; i++)
        cp16(adst + i * 4096, asrc + (size_t)i * 40960, 1);
    #pragma unroll
    for (int jj = 0; jj < CPIT; jj++) {
        int idx = tid + jj * 256;
        int v = idx < NB8;
        int n = idx >> 3, q = idx & 7;
        uint32_t d = (uint32_t)(n * 128 + ((q ^ (n & 7)) << 4));
        cp16(su + BOFF + d, BhT + n * 512 + q * 8, v);
    }
    asm volatile("cp.async.commit_group;" ::: "memory");

    #pragma unroll 1
    for (int kc = 0; kc < 8; kc++) {
        const int s = kc & 1;

        // stage s (A+B of chunk kc) ready; publish
        asm volatile("cp.async.wait_group 0;" ::: "memory");
        __syncthreads();
        // issue A(kc+1) + B(kc+1) into stage s^1 (all warps past its reads)
        if (kc < 7) {
            const float* as2 = asrc + (kc + 1) * 64;
            const uint32_t ad2 = adst + (uint32_t)((s ^ 1) * AB);
            #pragma unroll
            for (int i = 0; i < 8; i++)
                cp16(ad2 + i * 4096, as2 + (size_t)i * 40960, 1);
            const uint32_t bdst = su + BOFF + (s ^ 1) * BB;
            const __half* bhs = BhT + (kc + 1) * 64;
            #pragma unroll
            for (int jj = 0; jj < CPIT; jj++) {
                int idx = tid + jj * 256;
                int v = idx < NB8;
                int n = idx >> 3, q = idx & 7;
                uint32_t d = (uint32_t)(n * 128 + ((q ^ (n & 7)) << 4));
                cp16(bdst + d, bhs + n * 512 + q * 8, v);
            }
            asm volatile("cp.async.commit_group;" ::: "memory");
        }

        // MMA on stage s
        const uint32_t aS    = (uint32_t)(s * AB);
        const uint32_t bBase = su + BOFF + s * BB;
        #pragma unroll
        for (int j = 0; j < 4; j++) {
            // A fragment: LDS f32 + convert (k-permuted layout matches B)
            uint32_t u1 = (uint32_t)(((4 * j + tig) ^ xr) << 4);
            float4 v1 = lds128(ac1 + aS + u1);
            float4 v2 = lds128(ac1 + aS + 2048 + u1);   // row r1+8, same xr
            uint32_t ah[4];
            ah[0] = f16x2_rn(v1.x, v1.y);
            ah[2] = f16x2_rn(v1.z, v1.w);
            ah[1] = f16x2_rn(v2.x, v2.y);
            ah[3] = f16x2_rn(v2.z, v2.w);
            // B fragments + MMAs
            uint32_t bu = (uint32_t)(((2 * j + kuB) ^ sw) << 4);
            #pragma unroll
            for (int p = 0; p < PAIRS; p++) {
                uint32_t boff = (uint32_t)((16 * p + rBo) * 128) + bu;
                uint32_t bh[4];
                ldsm_x4(bh, bBase + boff);
                mma_f16(acc[2 * p],     ah, bh);
                mma_f16(acc[2 * p + 1], ah, bh + 2);
            }
            if (ODD) {
                uint32_t boff = (uint32_t)((16 * PAIRS + (lane & 7)) * 128) + bu;
                uint32_t bh[2];
                ldsm_x2(bh, bBase + boff);
                mma_f16(acc[NT - 1], ah, bh);
            }
        }
    }

    // ---- epilogue: bias + scatter ----
    const int g = lane >> 2;

    int   coff[NT][2];
    float cb[NT][2];
    #pragma unroll
    for (int t = 0; t < NT; t++) {
        #pragma unroll
        for (int h = 0; h < 2; h++) {
            int o = CO + 8 * t + 2 * tig + h;
            if (o < NREAL) {
                int p   = o / (GS * 3);
                int rem = o - p * (GS * 3);
                int joff = (GS == 5) ? ((rem < 3) ? rem : rem + 18) : (jb3 + rem);
                coff[t][h] = p * 51 + joff;
                cb[t][h]   = bias[o];
            } else {
                coff[t][h] = -1;
                cb[t][h]   = 0.f;
            }
        }
    }

    #pragma unroll
    for (int half = 0; half < 2; half++) {
        int m  = m0 + 16 * wid + g + 8 * half;
        int b  = m / 27;
        int tp = m - b * 27;
        size_t obase = (size_t)b * 12393 + (size_t)tp * 459;
        #pragma unroll
        for (int t = 0; t < NT; t++) {
            float v0 = acc[t][2 * half];
            float v1 = acc[t][2 * half + 1];
            if (coff[t][0] >= 0) out[obase + coff[t][0]] = v0 + cb[t][0];
            if (coff[t][1] >= 0) out[obase + coff[t][1]] = v1 + cb[t][1];
        }
    }
}

// One fused kernel. blockIdx.x = variant: 0..3 -> groups 0,1,3,4 (NPAD=88);
// 4,5 -> group 2 halves (NPAD=72). blockIdx.y = m-block (same token rows
// across all 6 variants -> L2 reuse for g2 double-read + output merging).
__global__ void __launch_bounds__(256, 2) dec_all(
    const float* __restrict__ tokens,
    const float* __restrict__ b0, const float* __restrict__ b1,
    const float* __restrict__ b2, const float* __restrict__ b3,
    const float* __restrict__ b4,
    float* __restrict__ out)
{
    int y = blockIdx.x;
    if (y < 4) {
        int rowbase, gidx, jb3;
        const float* bias;
        switch (y) {
            case 0:  rowbase = 0;   gidx = 0; jb3 = 3;  bias = b0; break;
            case 1:  rowbase = 88;  gidx = 1; jb3 = 12; bias = b1; break;
            case 2:  rowbase = 320; gidx = 3; jb3 = 33; bias = b3; break;
            default: rowbase = 408; gidx = 4; jb3 = 42; bias = b4; break;
        }
        decode_core<88, 3, 0>(tokens, g_Bh + rowbase * 512, bias, out, gidx, jb3);
    } else if (y == 4) {
        decode_core<72, 5, 0>(tokens, g_Bh + 176 * 512, b2, out, 2, 0);
    } else {
        decode_core<72, 5, 72>(tokens, g_Bh + 248 * 512, b2, out, 2, 0);
    }
}

extern "C" void kernel_launch(void* const* d_in, const int* in_sizes, int n_in,
                              void* d_out, int out_size) {
    const float* tokens = (const float*)d_in[0];
    const float* W[5];
    const float* B[5];
    for (int i = 0; i < 5; i++) {
        W[i] = (const float*)d_in[1 + 2 * i];
        B[i] = (const float*)d_in[2 + 2 * i];
    }
    float* out = (float*)d_out;

    // dyn smem: 2 A stages (32KB) + 2 B stages (<=11.25KB) = 88064 B max
    const int smem_sz = 2 * 32768 + 2 * 88 * 128;
    cudaFuncSetAttribute(dec_all, cudaFuncAttributeMaxDynamicSharedMemorySize, smem_sz);

    prep_B<<<(496 * 128 + 255) / 256, 256>>>(W[0], W[1], W[2], W[3], W[4]);
    dec_all<<<dim3(6, 216), 256, smem_sz>>>(tokens, B[0], B[1], B[2], B[3], B[4], out);
}